// round 12
// baseline (speedup 1.0000x reference)
#include <cuda_runtime.h>
#include <cuda_bf16.h>
#include <cstdint>

// MaskedPooling: out[b,d] = sum_t x[b,t,d]*keep[b,t] / sum_t keep[b,t]
// x: [32,4096,512] f32, mask: [32,4096] int32 (nonzero = excluded).
// R12: LDG-gather mainloop replaced by cp.async.bulk (TMA bulk) gather into a
// 4-stage smem ring + LDS accumulate. R4-R11 showed DRAM pinned 50-61% across
// occ 21-58% / MLP 4-16 -> suspect cross-CTA L1tex wavefront-queue contention;
// bulk-copy path bypasses L1tex entirely. Compaction + fused last-CTA
// reduction unchanged.

#define B_DIM 32
#define T_DIM 4096
#define D_DIM 512
#define S_SPLIT 32
#define ROWS (T_DIM / S_SPLIT)   // 128
#define TPB 128                  // 128 threads * float4 = 512 floats = D
#define DSTRIDE (D_DIM / 4)      // 128 float4 per row
#define ROW_BYTES (D_DIM * 4)    // 2048
#define GROUP 4                  // rows per pipeline stage
#define NSTAGE 4                 // stages (32 KB data ring)

__device__ float g_partial[B_DIM * S_SPLIT * D_DIM];  // 2 MB scratch
__device__ float g_count[B_DIM * S_SPLIT];
__device__ int   g_sem[B_DIM];                        // zero-init; self-resetting

#define ACC4(A, V) do { (A).x += (V).x; (A).y += (V).y; (A).z += (V).z; (A).w += (V).w; } while (0)

__device__ __forceinline__ uint32_t smem_u32(const void* p) {
    uint32_t a;
    asm("{ .reg .u64 t; cvta.to.shared.u64 t, %1; cvt.u32.u64 %0, t; }"
        : "=r"(a) : "l"(p));
    return a;
}

__device__ __forceinline__ void mbar_init(uint32_t mbar, uint32_t count) {
    asm volatile("mbarrier.init.shared.b64 [%0], %1;" :: "r"(mbar), "r"(count) : "memory");
}
__device__ __forceinline__ void mbar_expect_tx(uint32_t mbar, uint32_t bytes) {
    asm volatile("mbarrier.arrive.expect_tx.shared.b64 _, [%0], %1;"
                 :: "r"(mbar), "r"(bytes) : "memory");
}
__device__ __forceinline__ void bulk_copy_g2s(uint32_t dst_smem, const void* src,
                                              uint32_t bytes, uint32_t mbar) {
    asm volatile("cp.async.bulk.shared::cta.global.mbarrier::complete_tx::bytes "
                 "[%0], [%1], %2, [%3];"
                 :: "r"(dst_smem), "l"(src), "r"(bytes), "r"(mbar) : "memory");
}
__device__ __forceinline__ void mbar_wait_parity(uint32_t mbar, uint32_t parity) {
    uint32_t done;
    asm volatile(
        "{\n\t.reg .pred p;\n\t"
        "mbarrier.try_wait.parity.acquire.cta.shared::cta.b64 p, [%1], %2;\n\t"
        "selp.b32 %0, 1, 0, p;\n\t}"
        : "=r"(done) : "r"(mbar), "r"(parity) : "memory");
    if (!done) {
        asm volatile(
            "{\n\t.reg .pred P1;\n\t"
            "WAIT_LOOP_%=:\n\t"
            "mbarrier.try_wait.parity.acquire.cta.shared::cta.b64 P1, [%0], %1, 0x989680;\n\t"
            "@P1 bra.uni WAIT_DONE_%=;\n\t"
            "bra.uni WAIT_LOOP_%=;\n\t"
            "WAIT_DONE_%=:\n\t}"
            :: "r"(mbar), "r"(parity) : "memory");
    }
}

__global__ __launch_bounds__(TPB) void mp_fused_kernel(
    const float* __restrict__ x, const int* __restrict__ mask,
    float* __restrict__ out) {
    const int s = blockIdx.x;   // T-chunk
    const int b = blockIdx.y;   // batch
    const int tid = threadIdx.x;
    const int lane = tid & 31;
    const int wid = tid >> 5;
    const int t0 = s * ROWS;

    __shared__ __align__(128) char ring[NSTAGE * GROUP * ROW_BYTES];  // 32 KB
    __shared__ __align__(8) unsigned long long full_bar[NSTAGE];
    __shared__ int m[ROWS];
    __shared__ int offbuf[ROWS];     // byte offsets of kept rows
    __shared__ int wcnt[5];
    __shared__ bool isLast;

    // stage mask chunk (128 int32 = 512 B)
    if (tid < ROWS / 4) {
        reinterpret_cast<int4*>(m)[tid] =
            reinterpret_cast<const int4*>(mask + b * T_DIM + t0)[tid];
    }
    if (tid == 0) {
        #pragma unroll
        for (int st = 0; st < NSTAGE; st++)
            mbar_init(smem_u32(&full_bar[st]), 1);
    }
    __syncthreads();

    // compact kept-row byte offsets: single ballot round (ROWS == TPB)
    bool kflag = (m[tid] == 0);
    unsigned bal = __ballot_sync(0xffffffffu, kflag);
    if (lane == 0) wcnt[wid] = __popc(bal);
    __syncthreads();
    if (tid == 0) {
        int sum = 0;
        #pragma unroll
        for (int j = 0; j < 4; j++) { int c = wcnt[j]; wcnt[j] = sum; sum += c; }
        wcnt[4] = sum;
    }
    __syncthreads();
    const int nkeep = wcnt[4];
    if (kflag) {
        int pos = wcnt[wid] + __popc(bal & ((1u << lane) - 1u));
        offbuf[pos] = tid * ROW_BYTES;
    }
    __syncthreads();

    const char* xchunk = reinterpret_cast<const char*>(
        x + ((size_t)b * T_DIM + t0) * D_DIM);
    const uint32_t ring_s = smem_u32(ring);
    const int ngroups = (nkeep + GROUP - 1) / GROUP;

    // prologue: fill up to NSTAGE stages
    if (tid == 0) {
        int npro = ngroups < NSTAGE ? ngroups : NSTAGE;
        for (int g = 0; g < npro; g++) {
            int cnt = nkeep - g * GROUP; if (cnt > GROUP) cnt = GROUP;
            uint32_t mb = smem_u32(&full_bar[g]);
            mbar_expect_tx(mb, cnt * ROW_BYTES);
            for (int j = 0; j < cnt; j++)
                bulk_copy_g2s(ring_s + (g * GROUP + j) * ROW_BYTES,
                              xchunk + offbuf[g * GROUP + j], ROW_BYTES, mb);
        }
    }

    float4 acc0 = make_float4(0.f, 0.f, 0.f, 0.f);
    float4 acc1 = make_float4(0.f, 0.f, 0.f, 0.f);

    for (int g = 0; g < ngroups; g++) {
        const int st = g & (NSTAGE - 1);
        const uint32_t parity = (g / NSTAGE) & 1;
        mbar_wait_parity(smem_u32(&full_bar[st]), parity);

        const float4* stage = reinterpret_cast<const float4*>(
            ring + st * GROUP * ROW_BYTES) + tid;
        const int cnt = min(GROUP, nkeep - g * GROUP);
        if (cnt == GROUP) {
            float4 v0 = stage[0 * DSTRIDE];
            float4 v1 = stage[1 * DSTRIDE];
            float4 v2 = stage[2 * DSTRIDE];
            float4 v3 = stage[3 * DSTRIDE];
            ACC4(acc0, v0); ACC4(acc1, v1); ACC4(acc0, v2); ACC4(acc1, v3);
        } else {
            for (int j = 0; j < cnt; j++) {  // uniform branch, last group only
                float4 v = stage[j * DSTRIDE];
                ACC4(acc0, v);
            }
        }
        __syncthreads();  // whole CTA done reading this stage

        const int gn = g + NSTAGE;
        if (tid == 0 && gn < ngroups) {
            int cnt2 = nkeep - gn * GROUP; if (cnt2 > GROUP) cnt2 = GROUP;
            uint32_t mb = smem_u32(&full_bar[st]);
            mbar_expect_tx(mb, cnt2 * ROW_BYTES);
            for (int j = 0; j < cnt2; j++)
                bulk_copy_g2s(ring_s + (st * GROUP + j) * ROW_BYTES,
                              xchunk + offbuf[gn * GROUP + j], ROW_BYTES, mb);
        }
    }
    ACC4(acc0, acc1);

    reinterpret_cast<float4*>(g_partial)[(size_t)(b * S_SPLIT + s) * DSTRIDE + tid] = acc0;
    if (tid == 0) g_count[b * S_SPLIT + s] = (float)nkeep;

    // ALL warps must finish partial stores before this CTA arrives.
    __syncthreads();
    __threadfence();
    if (tid == 0) {
        int v = atomicAdd(&g_sem[b], 1);
        isLast = (v == S_SPLIT - 1);
    }
    __syncthreads();

    if (isLast) {
        float denom = 0.f;
        #pragma unroll 8
        for (int ss = 0; ss < S_SPLIT; ss++) denom += g_count[b * S_SPLIT + ss];

        float4 r0 = make_float4(0.f, 0.f, 0.f, 0.f);
        float4 r1 = make_float4(0.f, 0.f, 0.f, 0.f);
        const float4* gp = reinterpret_cast<const float4*>(g_partial);
        #pragma unroll 8
        for (int ss = 0; ss < S_SPLIT; ss += 2) {
            float4 v0 = gp[(size_t)(b * S_SPLIT + ss) * DSTRIDE + tid];
            float4 v1 = gp[(size_t)(b * S_SPLIT + ss + 1) * DSTRIDE + tid];
            ACC4(r0, v0); ACC4(r1, v1);
        }
        ACC4(r0, r1);
        float inv = 1.f / denom;
        r0.x *= inv; r0.y *= inv; r0.z *= inv; r0.w *= inv;
        reinterpret_cast<float4*>(out)[(size_t)b * DSTRIDE + tid] = r0;

        if (tid == 0) g_sem[b] = 0;  // reset for next graph replay
    }
}

extern "C" void kernel_launch(void* const* d_in, const int* in_sizes, int n_in,
                              void* d_out, int out_size) {
    const float* x = (const float*)d_in[0];
    const int* mask = (const int*)d_in[1];
    float* out = (float*)d_out;

    dim3 grid(S_SPLIT, B_DIM);
    mp_fused_kernel<<<grid, TPB>>>(x, mask, out);
}

// round 14
// speedup vs baseline: 1.2051x; 1.2051x over previous
#include <cuda_runtime.h>
#include <cuda_bf16.h>

// MaskedPooling: out[b,d] = sum_t x[b,t,d]*keep[b,t] / sum_t keep[b,t]
// x: [32,4096,512] f32, mask: [32,4096] int32 (nonzero = excluded).
// R13: persistent CTAs (148*7) + dynamic chunk stealing over 1024 chunks of
// 128 rows. Removes per-SM CTA-count quantization + nkeep-variance tail that
// R10's static grid paid (~2-3us). Mainloop = R10's depth-1 batch-4 software
// pipeline (best measured: 4.85 TB/s; R11 depth-2 and R12 TMA both worse ->
// DRAM-side gather-pattern ceiling, not SM-side).

#define B_DIM 32
#define T_DIM 4096
#define D_DIM 512
#define S_SPLIT 32
#define ROWS (T_DIM / S_SPLIT)   // 128 rows per chunk
#define NCHUNK (B_DIM * S_SPLIT) // 1024
#define TPB 128                  // 128 threads * float4 = 512 floats = D
#define DSTRIDE (D_DIM / 4)      // 128 float4 per row
#define GRID 1036                // 148 SMs * 7 CTAs

__device__ float g_partial[B_DIM * S_SPLIT * D_DIM];  // 2 MB scratch
__device__ float g_count[B_DIM * S_SPLIT];
__device__ int   g_sem[B_DIM];          // zero-init; self-resetting
__device__ unsigned g_next;             // chunk-steal counter (self-resetting)
__device__ unsigned g_done;             // CTA completion counter (self-resetting)

#define ACC4(A, V) do { (A).x += (V).x; (A).y += (V).y; (A).z += (V).z; (A).w += (V).w; } while (0)

__global__ __launch_bounds__(TPB, 7) void mp_fused_kernel(
    const float* __restrict__ x, const int* __restrict__ mask,
    float* __restrict__ out) {
    const int tid = threadIdx.x;
    const int lane = tid & 31;
    const int wid = tid >> 5;

    __shared__ int m[ROWS];
    __shared__ short idxbuf[ROWS];
    __shared__ int wcnt[5];
    __shared__ bool isLast;
    __shared__ unsigned curChunk;

    for (;;) {
        // steal next chunk
        if (tid == 0) curChunk = atomicAdd(&g_next, 1u);
        __syncthreads();
        const unsigned c = curChunk;
        if (c >= NCHUNK) break;
        const int b = c >> 5;          // c / S_SPLIT
        const int s = c & (S_SPLIT - 1);
        const int t0 = s * ROWS;

        // stage mask chunk (128 int32 = 512 B)
        if (tid < ROWS / 4) {
            reinterpret_cast<int4*>(m)[tid] =
                reinterpret_cast<const int4*>(mask + b * T_DIM + t0)[tid];
        }
        __syncthreads();

        // compact kept-row indices: single ballot round (ROWS == TPB)
        bool kflag = (m[tid] == 0);
        unsigned bal = __ballot_sync(0xffffffffu, kflag);
        if (lane == 0) wcnt[wid] = __popc(bal);
        __syncthreads();
        if (tid == 0) {
            int sum = 0;
            #pragma unroll
            for (int j = 0; j < 4; j++) { int cc = wcnt[j]; wcnt[j] = sum; sum += cc; }
            wcnt[4] = sum;
        }
        __syncthreads();
        const int nkeep = wcnt[4];
        if (kflag) {
            int pos = wcnt[wid] + __popc(bal & ((1u << lane) - 1u));
            idxbuf[pos] = (short)tid;
        }
        __syncthreads();

        const float4* xp = reinterpret_cast<const float4*>(
            x + ((size_t)b * T_DIM + t0) * D_DIM);

        float4 acc0 = make_float4(0.f, 0.f, 0.f, 0.f);
        float4 acc1 = make_float4(0.f, 0.f, 0.f, 0.f);

        // depth-1 batch-4 software pipeline (R10): loads always in flight
        int i = 0;
        if (nkeep >= 8) {
            float4 b0 = __ldcs(&xp[(size_t)idxbuf[0] * DSTRIDE + tid]);
            float4 b1 = __ldcs(&xp[(size_t)idxbuf[1] * DSTRIDE + tid]);
            float4 b2 = __ldcs(&xp[(size_t)idxbuf[2] * DSTRIDE + tid]);
            float4 b3 = __ldcs(&xp[(size_t)idxbuf[3] * DSTRIDE + tid]);
            for (i = 4; i + 4 <= nkeep; i += 4) {
                float4 n0 = __ldcs(&xp[(size_t)idxbuf[i + 0] * DSTRIDE + tid]);
                float4 n1 = __ldcs(&xp[(size_t)idxbuf[i + 1] * DSTRIDE + tid]);
                float4 n2 = __ldcs(&xp[(size_t)idxbuf[i + 2] * DSTRIDE + tid]);
                float4 n3 = __ldcs(&xp[(size_t)idxbuf[i + 3] * DSTRIDE + tid]);
                ACC4(acc0, b0); ACC4(acc1, b1); ACC4(acc0, b2); ACC4(acc1, b3);
                b0 = n0; b1 = n1; b2 = n2; b3 = n3;
            }
            ACC4(acc0, b0); ACC4(acc1, b1); ACC4(acc0, b2); ACC4(acc1, b3);
        }
        // predicated tail batches: clamped indices, zero weights
        while (i < nkeep) {
            #pragma unroll
            for (int j = 0; j < 4; j++) {
                int k = i + j;
                bool ok = (k < nkeep);
                int r = idxbuf[ok ? k : i];
                float w = ok ? 1.f : 0.f;
                float4 v = __ldcs(&xp[(size_t)r * DSTRIDE + tid]);
                acc0.x = fmaf(w, v.x, acc0.x);
                acc0.y = fmaf(w, v.y, acc0.y);
                acc0.z = fmaf(w, v.z, acc0.z);
                acc0.w = fmaf(w, v.w, acc0.w);
            }
            i += 4;
        }
        ACC4(acc0, acc1);

        reinterpret_cast<float4*>(g_partial)[(size_t)c * DSTRIDE + tid] = acc0;
        if (tid == 0) g_count[c] = (float)nkeep;

        // ALL warps must finish partial stores before this CTA arrives.
        __syncthreads();
        __threadfence();
        if (tid == 0) {
            int v = atomicAdd(&g_sem[b], 1);
            isLast = (v == S_SPLIT - 1);
        }
        __syncthreads();

        if (isLast) {
            float denom = 0.f;
            #pragma unroll 8
            for (int ss = 0; ss < S_SPLIT; ss++) denom += g_count[b * S_SPLIT + ss];

            float4 r0 = make_float4(0.f, 0.f, 0.f, 0.f);
            float4 r1 = make_float4(0.f, 0.f, 0.f, 0.f);
            const float4* gp = reinterpret_cast<const float4*>(g_partial);
            #pragma unroll 8
            for (int ss = 0; ss < S_SPLIT; ss += 2) {
                float4 v0 = gp[(size_t)(b * S_SPLIT + ss) * DSTRIDE + tid];
                float4 v1 = gp[(size_t)(b * S_SPLIT + ss + 1) * DSTRIDE + tid];
                ACC4(r0, v0); ACC4(r1, v1);
            }
            ACC4(r0, r1);
            float inv = 1.f / denom;
            r0.x *= inv; r0.y *= inv; r0.z *= inv; r0.w *= inv;
            reinterpret_cast<float4*>(out)[(size_t)b * DSTRIDE + tid] = r0;

            if (tid == 0) g_sem[b] = 0;  // reset for next graph replay
        }
        __syncthreads();  // protect shared state before next iteration
    }

    // self-reset steal counters for graph replay: last CTA to stop stealing
    // resets both (all atomicAdds on g_next have already happened).
    if (tid == 0) {
        unsigned d = atomicAdd(&g_done, 1u);
        if (d == GRID - 1) {
            g_next = 0u;
            g_done = 0u;
            __threadfence();
        }
    }
}

extern "C" void kernel_launch(void* const* d_in, const int* in_sizes, int n_in,
                              void* d_out, int out_size) {
    const float* x = (const float*)d_in[0];
    const int* mask = (const int*)d_in[1];
    float* out = (float*)d_out;

    mp_fused_kernel<<<GRID, TPB>>>(x, mask, out);
}